// round 3
// baseline (speedup 1.0000x reference)
#include <cuda_runtime.h>
#include <math.h>

#define BB 8
#define TT 50
#define SS 256
#define HH 512
#define NL 4
#define NVOC 50000
#define NVEXT 50256
#define ROWS (BB*TT)                 /* 400 */
#define OUT_ATT_OFF (ROWS*NVEXT)     /* 20,102,400 */

// ---------------- device scratch (static: no allocation) ----------------
__device__ float    g_tar_emb[ROWS*HH];
__device__ float    g_x[NL*ROWS*HH];          // per-layer GRU outputs; layer 3 = masked dec_out
__device__ float    g_h2[2][NL*BB*HH];        // double-buffered hidden state
__device__ int      g_len[BB];
__device__ float    g_e1[BB*SS*HH];
__device__ float    g_e2[ROWS*HH];
__device__ float    g_allout[ROWS*2*HH];      // [weighted | dec_out]
__device__ float    g_mid[ROWS*HH];
__device__ float    g_logits[ROWS*NVEXT];     // ~80 MB
__device__ float    g_atten[ROWS*SS];
__device__ float    g_gate[ROWS];
__device__ float    g_rowmax[ROWS];
__device__ float    g_rowsum[ROWS];
__device__ unsigned g_bar;

// ---------------- setup: lengths, barrier reset, h0 copy ----------------
__global__ void setup_kernel(const int* __restrict__ tar, const float* __restrict__ hidden)
{
    int tid = threadIdx.x;
    if (tid == 0) g_bar = 0u;
    if (tid < BB) {
        int c = 0;
        for (int t = 0; t < TT; ++t) c += (tar[tid*TT + t] > 0) ? 1 : 0;
        g_len[tid] = (c < 1) ? 1 : c;
    }
    for (int i = tid; i < NL*BB*HH; i += blockDim.x)
        g_h2[0][i] = hidden[i];
}

// ---------------- embedding gather (padding_idx=0 -> zero row) ----------
__global__ void embed_kernel(const int* __restrict__ tar, const float* __restrict__ emb)
{
    int row = blockIdx.x;                 // b*TT + t
    int tid = threadIdx.x;                // 128 threads, float4 each
    int idx = tar[row];
    float4 v = make_float4(0.f, 0.f, 0.f, 0.f);
    if (idx != 0)
        v = ((const float4*)(emb + (size_t)idx * HH))[tid];
    ((float4*)(g_tar_emb + (size_t)row * HH))[tid] = v;
}

// ---------------- GRU: layer-pipelined persistent kernel ----------------
#define GRU_BLOCKS 128
#define DOT4(acc, w, v) acc += (w).x*(v).x + (w).y*(v).y + (w).z*(v).z + (w).w*(v).w

__global__ void __launch_bounds__(128, 1)
gru_kernel(const float* __restrict__ wih, const float* __restrict__ whh,
           const float* __restrict__ bih, const float* __restrict__ bhh)
{
    const int bid = blockIdx.x;
    const int l    = bid >> 5;            // 32 blocks per layer
    const int sub  = bid & 31;
    const int b    = sub >> 2;            // 4 blocks per batch row
    const int jblk = (sub & 3) << 7;      // 128-wide j slice
    const int tid  = threadIdx.x;
    const int jg   = jblk + tid;          // output index within H

    __shared__ float4 xs4[HH/4];
    __shared__ float4 hs4[HH/4];
    float* xs = (float*)xs4;
    float* hs = (float*)hs4;

    const float4* wiR = (const float4*)(wih + ((size_t)l*3*HH + jg) * HH);
    const float4* wiZ = wiR + (HH*HH/4);
    const float4* wiN = wiZ + (HH*HH/4);
    const float4* whR = (const float4*)(whh + ((size_t)l*3*HH + jg) * HH);
    const float4* whZ = whR + (HH*HH/4);
    const float4* whN = whZ + (HH*HH/4);

    const float biR = bih[l*3*HH + jg];
    const float biZ = bih[l*3*HH + HH + jg];
    const float biN = bih[l*3*HH + 2*HH + jg];
    const float bhR = bhh[l*3*HH + jg];
    const float bhZ = bhh[l*3*HH + HH + jg];
    const float bhN = bhh[l*3*HH + 2*HH + jg];

    const int hoff = (l*BB + b) * HH;
    const int lenb = g_len[b];

    unsigned goal = 0u;
    for (int step = 0; step < TT + NL - 1; ++step) {
        const int t = step - l;
        const int p = step & 1;
        const bool active = (t >= 0) && (t < TT);

        if (active) {
            const float* xsrc = (l == 0)
                ? (g_tar_emb + (size_t)(b*TT + t) * HH)
                : (g_x + ((size_t)(l-1)*ROWS + b*TT + t) * HH);
            xs4[tid] = ((const float4*)xsrc)[tid];
            hs4[tid] = ((const float4*)(g_h2[p] + hoff))[tid];
            __syncthreads();

            float ar = 0.f, az = 0.f, an = 0.f, cr = 0.f, cz = 0.f, cn = 0.f;
#pragma unroll 8
            for (int k = 0; k < HH/4; ++k) {
                float4 xv = xs4[k], hv = hs4[k], w;
                w = wiR[k]; DOT4(ar, w, xv);
                w = wiZ[k]; DOT4(az, w, xv);
                w = wiN[k]; DOT4(an, w, xv);
                w = whR[k]; DOT4(cr, w, hv);
                w = whZ[k]; DOT4(cz, w, hv);
                w = whN[k]; DOT4(cn, w, hv);
            }
            float r = 1.f / (1.f + expf(-(ar + biR + cr + bhR)));
            float z = 1.f / (1.f + expf(-(az + biZ + cz + bhZ)));
            float n = tanhf(an + biN + r * (cn + bhN));
            float hold = hs[jg];
            float hnew = (1.f - z) * n + z * hold;
            g_h2[p ^ 1][hoff + jg] = hnew;
            float ov = hnew;
            if (l == NL-1 && t >= lenb) ov = 0.f;
            g_x[((size_t)l*ROWS + b*TT + t) * HH + jg] = ov;
        } else {
            g_h2[p ^ 1][hoff + jg] = g_h2[p][hoff + jg];
        }

        // grid barrier (monotonic counter; reset by setup_kernel each launch)
        __syncthreads();
        if (tid == 0) {
            __threadfence();
            atomicAdd(&g_bar, 1u);
            goal += GRU_BLOCKS;
            while (*(volatile unsigned*)&g_bar < goal) __nanosleep(64);
            __threadfence();
        }
        __syncthreads();
    }
}

// ---------------- generic SGEMM: C[m,n] = bias[n] + sum_k A[m,k]*W[n,k] ---
#define BM 128
#define BN 64
#define BKK 16
__global__ void __launch_bounds__(256)
sgemm_tn(const float* __restrict__ A, const float* __restrict__ W,
         const float* __restrict__ bias, float* __restrict__ C,
         int M, int N, int K)
{
    __shared__ float As[BKK][BM + 4];
    __shared__ float Ws[BKK][BN + 4];

    const int tid = threadIdx.x;
    const int m0 = blockIdx.y * BM;
    const int n0 = blockIdx.x * BN;
    const int tx = tid & 15;         // 0..15 -> 4 cols each
    const int ty = tid >> 4;         // 0..15 -> 8 rows each
    const int lr = tid >> 2;         // 0..63
    const int lk = (tid & 3) << 2;   // 0,4,8,12

    float acc[8][4];
#pragma unroll
    for (int i = 0; i < 8; ++i)
#pragma unroll
        for (int j = 0; j < 4; ++j) acc[i][j] = 0.f;

    for (int k0 = 0; k0 < K; k0 += BKK) {
#pragma unroll
        for (int h = 0; h < 2; ++h) {
            int m = m0 + lr + h*64;
            float4 v = make_float4(0.f,0.f,0.f,0.f);
            if (m < M) v = *(const float4*)(A + (size_t)m*K + k0 + lk);
            As[lk+0][lr + h*64] = v.x; As[lk+1][lr + h*64] = v.y;
            As[lk+2][lr + h*64] = v.z; As[lk+3][lr + h*64] = v.w;
        }
        {
            int n = n0 + lr;
            float4 v = make_float4(0.f,0.f,0.f,0.f);
            if (n < N) v = *(const float4*)(W + (size_t)n*K + k0 + lk);
            Ws[lk+0][lr] = v.x; Ws[lk+1][lr] = v.y;
            Ws[lk+2][lr] = v.z; Ws[lk+3][lr] = v.w;
        }
        __syncthreads();
#pragma unroll
        for (int k = 0; k < BKK; ++k) {
            float4 a0 = *(const float4*)&As[k][ty*8];
            float4 a1 = *(const float4*)&As[k][ty*8 + 4];
            float4 b0 = *(const float4*)&Ws[k][tx*4];
            float av[8] = {a0.x,a0.y,a0.z,a0.w,a1.x,a1.y,a1.z,a1.w};
            float bv[4] = {b0.x,b0.y,b0.z,b0.w};
#pragma unroll
            for (int i = 0; i < 8; ++i)
#pragma unroll
                for (int j = 0; j < 4; ++j)
                    acc[i][j] += av[i] * bv[j];
        }
        __syncthreads();
    }
#pragma unroll
    for (int i = 0; i < 8; ++i) {
        int m = m0 + ty*8 + i;
        if (m >= M) continue;
#pragma unroll
        for (int j = 0; j < 4; ++j) {
            int n = n0 + tx*4 + j;
            if (n < N) C[(size_t)m*N + n] = acc[i][j] + bias[n];
        }
    }
}

// ---------------- attention scores + softmax -> atten ----------------
__global__ void __launch_bounds__(256)
attn_kernel(const int* __restrict__ sou, const float* __restrict__ v_w,
            float* __restrict__ out)
{
    const int row = blockIdx.x;            // b*TT + t
    const int b = row / TT;
    const int tid = threadIdx.x;
    const int warp = tid >> 5, lane = tid & 31;
    const float NEG_INF = __int_as_float(0xff800000);

    __shared__ float e2s[HH];
    __shared__ float vs[HH];
    __shared__ float sc[SS];
    __shared__ float red[8];

    e2s[tid]       = g_e2[(size_t)row*HH + tid];
    e2s[tid + 256] = g_e2[(size_t)row*HH + tid + 256];
    vs[tid]        = v_w[tid];
    vs[tid + 256]  = v_w[tid + 256];
    __syncthreads();

    for (int s = warp; s < SS; s += 8) {
        const float* e1r = g_e1 + ((size_t)(b*SS + s)) * HH;
        float acc = 0.f;
#pragma unroll
        for (int k = 0; k < HH/32; ++k) {
            int h = lane + k*32;
            acc += tanhf(e1r[h] + e2s[h]) * vs[h];
        }
#pragma unroll
        for (int o = 16; o; o >>= 1) acc += __shfl_xor_sync(0xffffffffu, acc, o);
        if (lane == 0)
            sc[s] = (sou[b*SS + s] == 0) ? NEG_INF : acc;
    }
    __syncthreads();

    float v0 = sc[tid];
    // block max
    float m = v0;
#pragma unroll
    for (int o = 16; o; o >>= 1) m = fmaxf(m, __shfl_xor_sync(0xffffffffu, m, o));
    if (lane == 0) red[warp] = m;
    __syncthreads();
    float M = red[0];
#pragma unroll
    for (int w = 1; w < 8; ++w) M = fmaxf(M, red[w]);
    __syncthreads();
    // block sum of exp
    float e = __expf(v0 - M);
    float ssum = e;
#pragma unroll
    for (int o = 16; o; o >>= 1) ssum += __shfl_xor_sync(0xffffffffu, ssum, o);
    if (lane == 0) red[warp] = ssum;
    __syncthreads();
    float Ssum = 0.f;
#pragma unroll
    for (int w = 0; w < 8; ++w) Ssum += red[w];

    float p = e / Ssum;
    g_atten[(size_t)row*SS + tid] = p;
    out[OUT_ATT_OFF + (size_t)row*SS + tid] = p;
}

// ---------------- weighted = atten @ enc ; build all_out --------------
__global__ void __launch_bounds__(128)
weighted_kernel(const float* __restrict__ enc)
{
    const int row = blockIdx.x;
    const int b = row / TT;
    const int tid = threadIdx.x;           // 128 threads, float4 each

    __shared__ float att[SS];
    att[tid]       = g_atten[(size_t)row*SS + tid];
    att[tid + 128] = g_atten[(size_t)row*SS + tid + 128];
    __syncthreads();

    const float4* encb = (const float4*)enc;
    float4 acc = make_float4(0.f,0.f,0.f,0.f);
#pragma unroll 4
    for (int s = 0; s < SS; ++s) {
        float a = att[s];
        float4 ev = encb[((size_t)(b*SS + s)) * (HH/4) + tid];
        acc.x += a*ev.x; acc.y += a*ev.y; acc.z += a*ev.z; acc.w += a*ev.w;
    }
    float4* ao = (float4*)(g_allout + (size_t)row * 2*HH);
    ao[tid] = acc;                                             // weighted half
    float4 dv = ((const float4*)(g_x + ((size_t)3*ROWS + row)*HH))[tid];
    ao[HH/4 + tid] = dv;                                       // dec_out half
}

// ---------------- copy gate --------------------------------------------
__global__ void __launch_bounds__(128)
gate_kernel(const float* __restrict__ g1w, const float* __restrict__ g1b,
            const float* __restrict__ g2w, const float* __restrict__ g2b,
            const float* __restrict__ g3w, const float* __restrict__ g3b)
{
    const int row = blockIdx.x;
    const int tid = threadIdx.x;
    const int lane = tid & 31, warp = tid >> 5;
    __shared__ float red[4];

    const float* ao = g_allout + (size_t)row * 2*HH;
    const float* te = g_tar_emb + (size_t)row * HH;
    float part = 0.f;
    for (int i = tid; i < HH; i += 128)
        part += ao[i]*g1w[i] + ao[HH + i]*g2w[i] + te[i]*g3w[i];
#pragma unroll
    for (int o = 16; o; o >>= 1) part += __shfl_xor_sync(0xffffffffu, part, o);
    if (lane == 0) red[warp] = part;
    __syncthreads();
    if (tid == 0) {
        float s = red[0] + red[1] + red[2] + red[3] + g1b[0] + g2b[0] + g3b[0];
        g_gate[row] = 1.f / (1.f + expf(-s));
    }
}

// ---------------- logits row softmax stats ------------------------------
__global__ void __launch_bounds__(256)
stats_kernel(const int* __restrict__ ext_len)
{
    const int row = blockIdx.x;
    const int b = row / TT;
    const int tid = threadIdx.x;
    const int lane = tid & 31, warp = tid >> 5;
    const int limit = NVOC + ext_len[b];
    const float* lr = g_logits + (size_t)row * NVEXT;
    const float NEG_INF = __int_as_float(0xff800000);
    __shared__ float red[8];

    float m = NEG_INF;
    for (int c = tid; c < limit; c += 256) m = fmaxf(m, lr[c]);
#pragma unroll
    for (int o = 16; o; o >>= 1) m = fmaxf(m, __shfl_xor_sync(0xffffffffu, m, o));
    if (lane == 0) red[warp] = m;
    __syncthreads();
    float M = red[0];
#pragma unroll
    for (int w = 1; w < 8; ++w) M = fmaxf(M, red[w]);
    __syncthreads();

    float s = 0.f;
    for (int c = tid; c < limit; c += 256) s += __expf(lr[c] - M);
#pragma unroll
    for (int o = 16; o; o >>= 1) s += __shfl_xor_sync(0xffffffffu, s, o);
    if (lane == 0) red[warp] = s;
    __syncthreads();
    if (tid == 0) {
        float S = 0.f;
#pragma unroll
        for (int w = 0; w < 8; ++w) S += red[w];
        g_rowmax[row] = M;
        g_rowsum[row] = S;
    }
}

// ---------------- (1-gate)*softmax(logits) -> out -----------------------
__global__ void __launch_bounds__(256)
gen_kernel(const int* __restrict__ ext_len, float* __restrict__ out)
{
    const int row = blockIdx.y;
    const int c = blockIdx.x * 256 + threadIdx.x;
    if (c >= NVEXT) return;
    const int b = row / TT;
    const int limit = NVOC + ext_len[b];
    const float gate = g_gate[row];
    float val = 0.f;
    if (c < limit)
        val = __expf(g_logits[(size_t)row*NVEXT + c] - g_rowmax[row]) / g_rowsum[row];
    out[(size_t)row*NVEXT + c] = (1.f - gate) * val;
}

// ---------------- copy mechanism: scatter-add gate*atten ---------------
__global__ void __launch_bounds__(256)
scatter_kernel(const int* __restrict__ sou, float* __restrict__ out)
{
    const int row = blockIdx.x;
    const int b = row / TT;
    const int s = threadIdx.x;
    const float add = g_gate[row] * g_atten[(size_t)row*SS + s];
    atomicAdd(&out[(size_t)row*NVEXT + sou[b*SS + s]], add);
}

// ---------------- launcher ---------------------------------------------
extern "C" void kernel_launch(void* const* d_in, const int* in_sizes, int n_in,
                              void* d_out, int out_size)
{
    const int*   sou      = (const int*)  d_in[0];
    const int*   tar      = (const int*)  d_in[1];
    const float* hidden   = (const float*)d_in[2];
    const float* enc      = (const float*)d_in[3];
    const int*   ext_len  = (const int*)  d_in[4];
    const float* emb      = (const float*)d_in[5];
    const float* gru_wih  = (const float*)d_in[6];
    const float* gru_whh  = (const float*)d_in[7];
    const float* gru_bih  = (const float*)d_in[8];
    const float* gru_bhh  = (const float*)d_in[9];
    const float* fc_enc_w = (const float*)d_in[10];
    const float* fc_enc_b = (const float*)d_in[11];
    const float* fc_dec_w = (const float*)d_in[12];
    const float* fc_dec_b = (const float*)d_in[13];
    const float* v_w      = (const float*)d_in[14];
    const float* fc_out1_w= (const float*)d_in[15];
    const float* fc_out1_b= (const float*)d_in[16];
    const float* fc_out2_w= (const float*)d_in[17];
    const float* fc_out2_b= (const float*)d_in[18];
    const float* g1w      = (const float*)d_in[19];
    const float* g1b      = (const float*)d_in[20];
    const float* g2w      = (const float*)d_in[21];
    const float* g2b      = (const float*)d_in[22];
    const float* g3w      = (const float*)d_in[23];
    const float* g3b      = (const float*)d_in[24];
    float* out = (float*)d_out;

    float *p_e1, *p_e2, *p_x, *p_allout, *p_mid, *p_logits;
    cudaGetSymbolAddress((void**)&p_e1,     g_e1);
    cudaGetSymbolAddress((void**)&p_e2,     g_e2);
    cudaGetSymbolAddress((void**)&p_x,      g_x);
    cudaGetSymbolAddress((void**)&p_allout, g_allout);
    cudaGetSymbolAddress((void**)&p_mid,    g_mid);
    cudaGetSymbolAddress((void**)&p_logits, g_logits);
    const float* p_dec = p_x + (size_t)3*ROWS*HH;   // masked dec_out

    setup_kernel<<<1, 256>>>(tar, hidden);
    embed_kernel<<<ROWS, 128>>>(tar, emb);
    gru_kernel<<<GRU_BLOCKS, 128>>>(gru_wih, gru_whh, gru_bih, gru_bhh);

    // e1 = enc @ fc_enc_w^T + b   [2048, 512]
    sgemm_tn<<<dim3((HH+BN-1)/BN, (BB*SS+BM-1)/BM), 256>>>(enc, fc_enc_w, fc_enc_b, p_e1, BB*SS, HH, HH);
    // e2 = dec_out @ fc_dec_w^T + b  [400, 512]
    sgemm_tn<<<dim3((HH+BN-1)/BN, (ROWS+BM-1)/BM), 256>>>(p_dec, fc_dec_w, fc_dec_b, p_e2, ROWS, HH, HH);

    attn_kernel<<<ROWS, 256>>>(sou, v_w, out);
    weighted_kernel<<<ROWS, 128>>>(enc);
    gate_kernel<<<ROWS, 128>>>(g1w, g1b, g2w, g2b, g3w, g3b);

    // mid = all_out @ fc_out2_w^T + b  [400, 512], K=1024
    sgemm_tn<<<dim3((HH+BN-1)/BN, (ROWS+BM-1)/BM), 256>>>(p_allout, fc_out2_w, fc_out2_b, p_mid, ROWS, HH, 2*HH);
    // logits = mid @ fc_out1_w^T + b  [400, 50256]
    sgemm_tn<<<dim3((NVEXT+BN-1)/BN, (ROWS+BM-1)/BM), 256>>>(p_mid, fc_out1_w, fc_out1_b, p_logits, ROWS, NVEXT, HH);

    stats_kernel<<<ROWS, 256>>>(ext_len);
    gen_kernel<<<dim3((NVEXT+255)/256, ROWS), 256>>>(ext_len, out);
    scatter_kernel<<<ROWS, 256>>>(sou, out);
}

// round 10
// speedup vs baseline: 2.1720x; 2.1720x over previous
#include <cuda_runtime.h>
#include <math.h>

#define BB 8
#define TT 50
#define SS 256
#define HH 512
#define NL 4
#define NVOC 50000
#define NVEXT 50256
#define ROWS (BB*TT)                 /* 400 */
#define OUT_ATT_OFF (ROWS*NVEXT)

// ---------------- device scratch (static: no allocation) ----------------
__device__ float    g_tar_emb[ROWS*HH];
__device__ float    g_x[NL*ROWS*HH];          // per-layer GRU outputs; layer 3 = masked dec_out
__device__ float    g_h2[2][NL*BB*HH];        // double-buffered hidden state
__device__ int      g_len[BB];
__device__ float    g_e1[BB*SS*HH];
__device__ float    g_e2[ROWS*HH];
__device__ float    g_allout[ROWS*2*HH];
__device__ float    g_mid[ROWS*HH];
__device__ float    g_logits[ROWS*NVEXT];
__device__ float    g_atten[ROWS*SS];
__device__ float    g_gate[ROWS];
__device__ float    g_rowmax[ROWS];
__device__ float    g_rowsum[ROWS];
__device__ unsigned g_bar;

// ---------------- setup ----------------
__global__ void setup_kernel(const int* __restrict__ tar, const float* __restrict__ hidden)
{
    int tid = threadIdx.x;
    if (tid == 0) g_bar = 0u;
    if (tid < BB) {
        int c = 0;
        for (int t = 0; t < TT; ++t) c += (tar[tid*TT + t] > 0) ? 1 : 0;
        g_len[tid] = (c < 1) ? 1 : c;
    }
    for (int i = tid; i < NL*BB*HH; i += blockDim.x)
        g_h2[0][i] = hidden[i];
}

// ---------------- embedding gather ----------
__global__ void embed_kernel(const int* __restrict__ tar, const float* __restrict__ emb)
{
    int row = blockIdx.x;
    int tid = threadIdx.x;
    int idx = tar[row];
    float4 v = make_float4(0.f, 0.f, 0.f, 0.f);
    if (idx != 0)
        v = ((const float4*)(emb + (size_t)idx * HH))[tid];
    ((float4*)(g_tar_emb + (size_t)row * HH))[tid] = v;
}

// ---------------- GRU v2: batch-shared weights, k-split warps ----------------
// 128 blocks = 4 layers x 32 j-slices (16 j each). 128 threads:
//   jl = tid>>3 (0..15), ks = tid&7 (k-octet of 64).
// Per-block weight footprint 192KB -> L1-resident across steps.
#define GRU_BLOCKS 128
// NOTE: macro params must NOT be named x/y/z/w — member tokens after '.' get substituted.
#define DOT4(acc, u_, v_) acc += (u_).x*(v_).x + (u_).y*(v_).y + (u_).z*(v_).z + (u_).w*(v_).w
#define PHYS(k4) ((k4) ^ (((k4) >> 4) & 7))   /* smem bank swizzle on float4 index */

__global__ void __launch_bounds__(128, 1)
gru_kernel(const float* __restrict__ wih, const float* __restrict__ whh,
           const float* __restrict__ bih, const float* __restrict__ bhh)
{
    const int bid  = blockIdx.x;
    const int l    = bid >> 5;            // 32 blocks per layer
    const int jblk = (bid & 31) << 4;     // 16-wide j slice
    const int tid  = threadIdx.x;
    const int jl   = tid >> 3;            // 0..15
    const int ks   = tid & 7;             // 0..7  (64-k slice)
    const int j    = jblk + jl;

    __shared__ float4 xs4[BB][HH/4];
    __shared__ float4 hs4[BB][HH/4];
    __shared__ int    lens[BB];

    if (tid < BB) lens[tid] = g_len[tid];

    const float4* wiR = (const float4*)(wih + ((size_t)l*3*HH + j) * HH);
    const float4* wiZ = wiR + (HH*HH/4);
    const float4* wiN = wiZ + (HH*HH/4);
    const float4* whR = (const float4*)(whh + ((size_t)l*3*HH + j) * HH);
    const float4* whZ = whR + (HH*HH/4);
    const float4* whN = whZ + (HH*HH/4);

    const float biR = bih[l*3*HH + j];
    const float biZ = bih[l*3*HH + HH + j];
    const float biN = bih[l*3*HH + 2*HH + j];
    const float bhR = bhh[l*3*HH + j];
    const float bhZ = bhh[l*3*HH + HH + j];
    const float bhN = bhh[l*3*HH + 2*HH + j];

    unsigned goal = 0u;
    for (int step = 0; step < TT + NL - 1; ++step) {
        const int t = step - l;
        const int p = step & 1;
        const bool active = (t >= 0) && (t < TT);

        if (active) {
            // stage x and h for all 8 batches (swizzled)
#pragma unroll
            for (int q = 0; q < 8; ++q) {
                int idx = tid + q*128;          // 0..1023 over (b, k4)
                int b  = idx >> 7;
                int k4 = idx & 127;
                const float4* xsrc = (l == 0)
                    ? (const float4*)(g_tar_emb + (size_t)(b*TT + t) * HH)
                    : (const float4*)(g_x + ((size_t)(l-1)*ROWS + b*TT + t) * HH);
                xs4[b][PHYS(k4)] = xsrc[k4];
                hs4[b][PHYS(k4)] = ((const float4*)(g_h2[p] + (size_t)(l*BB + b) * HH))[k4];
            }
            __syncthreads();

            float aR[BB], aZ[BB], aN[BB], cR[BB], cZ[BB], cN[BB];
#pragma unroll
            for (int b = 0; b < BB; ++b) { aR[b]=0.f; aZ[b]=0.f; aN[b]=0.f; cR[b]=0.f; cZ[b]=0.f; cN[b]=0.f; }

#pragma unroll 4
            for (int i = 0; i < 16; ++i) {
                const int k4 = ks*16 + i;
                const float4 wr = wiR[k4], wz = wiZ[k4], wn = wiN[k4];
                const float4 vr = whR[k4], vz = whZ[k4], vn = whN[k4];
                const int kk = PHYS(k4);
#pragma unroll
                for (int b = 0; b < BB; ++b) {
                    const float4 xv = xs4[b][kk];
                    const float4 hv = hs4[b][kk];
                    DOT4(aR[b], wr, xv); DOT4(aZ[b], wz, xv); DOT4(aN[b], wn, xv);
                    DOT4(cR[b], vr, hv); DOT4(cZ[b], vz, hv); DOT4(cN[b], vn, hv);
                }
            }

            // reduce across the 8 k-octets (lane bits 0..2)
#pragma unroll
            for (int b = 0; b < BB; ++b) {
#pragma unroll
                for (int o = 1; o < 8; o <<= 1) {
                    aR[b] += __shfl_xor_sync(0xffffffffu, aR[b], o);
                    aZ[b] += __shfl_xor_sync(0xffffffffu, aZ[b], o);
                    aN[b] += __shfl_xor_sync(0xffffffffu, aN[b], o);
                    cR[b] += __shfl_xor_sync(0xffffffffu, cR[b], o);
                    cZ[b] += __shfl_xor_sync(0xffffffffu, cZ[b], o);
                    cN[b] += __shfl_xor_sync(0xffffffffu, cN[b], o);
                }
            }

            if (ks == 0) {
#pragma unroll
                for (int b = 0; b < BB; ++b) {
                    float r = 1.f / (1.f + expf(-(aR[b] + biR + cR[b] + bhR)));
                    float z = 1.f / (1.f + expf(-(aZ[b] + biZ + cZ[b] + bhZ)));
                    float n = tanhf(aN[b] + biN + r * (cN[b] + bhN));
                    float hold = ((const float*)&hs4[b][PHYS(j >> 2)])[j & 3];
                    float hnew = (1.f - z) * n + z * hold;
                    g_h2[p ^ 1][(size_t)(l*BB + b) * HH + j] = hnew;
                    float ov = hnew;
                    if (l == NL-1 && t >= lens[b]) ov = 0.f;
                    g_x[((size_t)l*ROWS + b*TT + t) * HH + j] = ov;
                }
            }
        } else {
            // carry hidden state forward: 128 threads cover 16j x 8b
            int b  = tid >> 4;
            int j2 = jblk + (tid & 15);
            g_h2[p ^ 1][(size_t)(l*BB + b) * HH + j2] =
                g_h2[p][(size_t)(l*BB + b) * HH + j2];
        }

        // grid barrier
        __syncthreads();
        if (tid == 0) {
            __threadfence();
            atomicAdd(&g_bar, 1u);
            goal += GRU_BLOCKS;
            while (*(volatile unsigned*)&g_bar < goal) __nanosleep(64);
            __threadfence();
        }
        __syncthreads();
    }
}

// ---------------- SGEMM v2: 64x128 tile, 8x8 microtile, double-buffered ----
// C[m,n] = bias[n] + sum_k A[m,k]*W[n,k]
#define BM 64
#define BN 128
#define BKK 16
__global__ void __launch_bounds__(128, 3)
sgemm_tn(const float* __restrict__ A, const float* __restrict__ W,
         const float* __restrict__ bias, float* __restrict__ C,
         int M, int N, int K)
{
    __shared__ float As[2][BKK][BM + 4];
    __shared__ float Bs[2][BKK][BN + 4];

    const int tid = threadIdx.x;
    const int m0 = blockIdx.y * BM;
    const int n0 = blockIdx.x * BN;
    const int tx = tid & 15;          // 16 x 8 cols = 128
    const int ty = tid >> 4;          // 8 x 8 rows = 64

    float acc[8][8];
#pragma unroll
    for (int i = 0; i < 8; ++i)
#pragma unroll
        for (int jj = 0; jj < 8; ++jj) acc[i][jj] = 0.f;

    float4 pa[2], pb[4];

    // prefetch tile 0
#pragma unroll
    for (int q = 0; q < 2; ++q) {
        int idx = tid + q*128; int row = idx >> 2, kq = idx & 3; int m = m0 + row;
        pa[q] = make_float4(0.f,0.f,0.f,0.f);
        if (m < M) pa[q] = *(const float4*)(A + (size_t)m*K + kq*4);
    }
#pragma unroll
    for (int q = 0; q < 4; ++q) {
        int idx = tid + q*128; int row = idx >> 2, kq = idx & 3; int n = n0 + row;
        pb[q] = make_float4(0.f,0.f,0.f,0.f);
        if (n < N) pb[q] = *(const float4*)(W + (size_t)n*K + kq*4);
    }
#pragma unroll
    for (int q = 0; q < 2; ++q) {
        int idx = tid + q*128; int row = idx >> 2, kq = idx & 3;
        As[0][kq*4+0][row] = pa[q].x; As[0][kq*4+1][row] = pa[q].y;
        As[0][kq*4+2][row] = pa[q].z; As[0][kq*4+3][row] = pa[q].w;
    }
#pragma unroll
    for (int q = 0; q < 4; ++q) {
        int idx = tid + q*128; int row = idx >> 2, kq = idx & 3;
        Bs[0][kq*4+0][row] = pb[q].x; Bs[0][kq*4+1][row] = pb[q].y;
        Bs[0][kq*4+2][row] = pb[q].z; Bs[0][kq*4+3][row] = pb[q].w;
    }
    __syncthreads();

    const int nk = K / BKK;
    for (int kb = 0; kb < nk; ++kb) {
        const int cur = kb & 1, nxt = cur ^ 1;
        const bool more = (kb + 1 < nk);
        if (more) {
            const int k0 = (kb + 1) * BKK;
#pragma unroll
            for (int q = 0; q < 2; ++q) {
                int idx = tid + q*128; int row = idx >> 2, kq = idx & 3; int m = m0 + row;
                pa[q] = make_float4(0.f,0.f,0.f,0.f);
                if (m < M) pa[q] = *(const float4*)(A + (size_t)m*K + k0 + kq*4);
            }
#pragma unroll
            for (int q = 0; q < 4; ++q) {
                int idx = tid + q*128; int row = idx >> 2, kq = idx & 3; int n = n0 + row;
                pb[q] = make_float4(0.f,0.f,0.f,0.f);
                if (n < N) pb[q] = *(const float4*)(W + (size_t)n*K + k0 + kq*4);
            }
        }
#pragma unroll
        for (int k = 0; k < BKK; ++k) {
            float4 a0 = *(const float4*)&As[cur][k][ty*8];
            float4 a1 = *(const float4*)&As[cur][k][ty*8 + 4];
            float4 b0 = *(const float4*)&Bs[cur][k][tx*8];
            float4 b1 = *(const float4*)&Bs[cur][k][tx*8 + 4];
            float av[8] = {a0.x,a0.y,a0.z,a0.w,a1.x,a1.y,a1.z,a1.w};
            float bv[8] = {b0.x,b0.y,b0.z,b0.w,b1.x,b1.y,b1.z,b1.w};
#pragma unroll
            for (int i = 0; i < 8; ++i)
#pragma unroll
                for (int jj = 0; jj < 8; ++jj)
                    acc[i][jj] += av[i] * bv[jj];
        }
        if (more) {
#pragma unroll
            for (int q = 0; q < 2; ++q) {
                int idx = tid + q*128; int row = idx >> 2, kq = idx & 3;
                As[nxt][kq*4+0][row] = pa[q].x; As[nxt][kq*4+1][row] = pa[q].y;
                As[nxt][kq*4+2][row] = pa[q].z; As[nxt][kq*4+3][row] = pa[q].w;
            }
#pragma unroll
            for (int q = 0; q < 4; ++q) {
                int idx = tid + q*128; int row = idx >> 2, kq = idx & 3;
                Bs[nxt][kq*4+0][row] = pb[q].x; Bs[nxt][kq*4+1][row] = pb[q].y;
                Bs[nxt][kq*4+2][row] = pb[q].z; Bs[nxt][kq*4+3][row] = pb[q].w;
            }
        }
        __syncthreads();
    }

#pragma unroll
    for (int i = 0; i < 8; ++i) {
        int m = m0 + ty*8 + i;
        if (m >= M) continue;
#pragma unroll
        for (int jj = 0; jj < 8; ++jj) {
            int n = n0 + tx*8 + jj;
            if (n < N) C[(size_t)m*N + n] = acc[i][jj] + bias[n];
        }
    }
}

// ---------------- attention scores + softmax -> atten ----------------
__global__ void __launch_bounds__(256)
attn_kernel(const int* __restrict__ sou, const float* __restrict__ v_w,
            float* __restrict__ out)
{
    const int row = blockIdx.x;
    const int b = row / TT;
    const int tid = threadIdx.x;
    const int warp = tid >> 5, lane = tid & 31;
    const float NEG_INF = __int_as_float(0xff800000);

    __shared__ float e2s[HH];
    __shared__ float vs[HH];
    __shared__ float sc[SS];
    __shared__ float red[8];

    e2s[tid]       = g_e2[(size_t)row*HH + tid];
    e2s[tid + 256] = g_e2[(size_t)row*HH + tid + 256];
    vs[tid]        = v_w[tid];
    vs[tid + 256]  = v_w[tid + 256];
    __syncthreads();

    for (int s = warp; s < SS; s += 8) {
        const float* e1r = g_e1 + ((size_t)(b*SS + s)) * HH;
        float acc = 0.f;
#pragma unroll
        for (int k = 0; k < HH/32; ++k) {
            int h = lane + k*32;
            acc += tanhf(e1r[h] + e2s[h]) * vs[h];
        }
#pragma unroll
        for (int o = 16; o; o >>= 1) acc += __shfl_xor_sync(0xffffffffu, acc, o);
        if (lane == 0)
            sc[s] = (sou[b*SS + s] == 0) ? NEG_INF : acc;
    }
    __syncthreads();

    float v0 = sc[tid];
    float m = v0;
#pragma unroll
    for (int o = 16; o; o >>= 1) m = fmaxf(m, __shfl_xor_sync(0xffffffffu, m, o));
    if (lane == 0) red[warp] = m;
    __syncthreads();
    float M = red[0];
#pragma unroll
    for (int w = 1; w < 8; ++w) M = fmaxf(M, red[w]);
    __syncthreads();
    float e = __expf(v0 - M);
    float ssum = e;
#pragma unroll
    for (int o = 16; o; o >>= 1) ssum += __shfl_xor_sync(0xffffffffu, ssum, o);
    if (lane == 0) red[warp] = ssum;
    __syncthreads();
    float Ssum = 0.f;
#pragma unroll
    for (int w = 0; w < 8; ++w) Ssum += red[w];

    float p = e / Ssum;
    g_atten[(size_t)row*SS + tid] = p;
    out[OUT_ATT_OFF + (size_t)row*SS + tid] = p;
}

// ---------------- weighted = atten @ enc ; build all_out --------------
__global__ void __launch_bounds__(128)
weighted_kernel(const float* __restrict__ enc)
{
    const int row = blockIdx.x;
    const int b = row / TT;
    const int tid = threadIdx.x;

    __shared__ float att[SS];
    att[tid]       = g_atten[(size_t)row*SS + tid];
    att[tid + 128] = g_atten[(size_t)row*SS + tid + 128];
    __syncthreads();

    const float4* encb = (const float4*)enc;
    float4 acc = make_float4(0.f,0.f,0.f,0.f);
#pragma unroll 4
    for (int s = 0; s < SS; ++s) {
        float a = att[s];
        float4 ev = encb[((size_t)(b*SS + s)) * (HH/4) + tid];
        acc.x += a*ev.x; acc.y += a*ev.y; acc.z += a*ev.z; acc.w += a*ev.w;
    }
    float4* ao = (float4*)(g_allout + (size_t)row * 2*HH);
    ao[tid] = acc;
    float4 dv = ((const float4*)(g_x + ((size_t)3*ROWS + row)*HH))[tid];
    ao[HH/4 + tid] = dv;
}

// ---------------- copy gate --------------------------------------------
__global__ void __launch_bounds__(128)
gate_kernel(const float* __restrict__ g1w, const float* __restrict__ g1b,
            const float* __restrict__ g2w, const float* __restrict__ g2b,
            const float* __restrict__ g3w, const float* __restrict__ g3b)
{
    const int row = blockIdx.x;
    const int tid = threadIdx.x;
    const int lane = tid & 31, warp = tid >> 5;
    __shared__ float red[4];

    const float* ao = g_allout + (size_t)row * 2*HH;
    const float* te = g_tar_emb + (size_t)row * HH;
    float part = 0.f;
    for (int i = tid; i < HH; i += 128)
        part += ao[i]*g1w[i] + ao[HH + i]*g2w[i] + te[i]*g3w[i];
#pragma unroll
    for (int o = 16; o; o >>= 1) part += __shfl_xor_sync(0xffffffffu, part, o);
    if (lane == 0) red[warp] = part;
    __syncthreads();
    if (tid == 0) {
        float s = red[0] + red[1] + red[2] + red[3] + g1b[0] + g2b[0] + g3b[0];
        g_gate[row] = 1.f / (1.f + expf(-s));
    }
}

// ---------------- logits row softmax stats ------------------------------
__global__ void __launch_bounds__(256)
stats_kernel(const int* __restrict__ ext_len)
{
    const int row = blockIdx.x;
    const int b = row / TT;
    const int tid = threadIdx.x;
    const int lane = tid & 31, warp = tid >> 5;
    const int limit = NVOC + ext_len[b];
    const float* lr = g_logits + (size_t)row * NVEXT;
    const float NEG_INF = __int_as_float(0xff800000);
    __shared__ float red[8];

    float m = NEG_INF;
    for (int c = tid; c < limit; c += 256) m = fmaxf(m, lr[c]);
#pragma unroll
    for (int o = 16; o; o >>= 1) m = fmaxf(m, __shfl_xor_sync(0xffffffffu, m, o));
    if (lane == 0) red[warp] = m;
    __syncthreads();
    float M = red[0];
#pragma unroll
    for (int w = 1; w < 8; ++w) M = fmaxf(M, red[w]);
    __syncthreads();

    float s = 0.f;
    for (int c = tid; c < limit; c += 256) s += __expf(lr[c] - M);
#pragma unroll
    for (int o = 16; o; o >>= 1) s += __shfl_xor_sync(0xffffffffu, s, o);
    if (lane == 0) red[warp] = s;
    __syncthreads();
    if (tid == 0) {
        float S = 0.f;
#pragma unroll
        for (int w = 0; w < 8; ++w) S += red[w];
        g_rowmax[row] = M;
        g_rowsum[row] = S;
    }
}

// ---------------- (1-gate)*softmax(logits) -> out -----------------------
__global__ void __launch_bounds__(256)
gen_kernel(const int* __restrict__ ext_len, float* __restrict__ out)
{
    const int row = blockIdx.y;
    const int c = blockIdx.x * 256 + threadIdx.x;
    if (c >= NVEXT) return;
    const int b = row / TT;
    const int limit = NVOC + ext_len[b];
    const float gate = g_gate[row];
    float val = 0.f;
    if (c < limit)
        val = __expf(g_logits[(size_t)row*NVEXT + c] - g_rowmax[row]) / g_rowsum[row];
    out[(size_t)row*NVEXT + c] = (1.f - gate) * val;
}

// ---------------- copy mechanism: scatter-add gate*atten ---------------
__global__ void __launch_bounds__(256)
scatter_kernel(const int* __restrict__ sou, float* __restrict__ out)
{
    const int row = blockIdx.x;
    const int b = row / TT;
    const int s = threadIdx.x;
    const float add = g_gate[row] * g_atten[(size_t)row*SS + s];
    atomicAdd(&out[(size_t)row*NVEXT + sou[b*SS + s]], add);
}

// ---------------- launcher ---------------------------------------------
extern "C" void kernel_launch(void* const* d_in, const int* in_sizes, int n_in,
                              void* d_out, int out_size)
{
    const int*   sou      = (const int*)  d_in[0];
    const int*   tar      = (const int*)  d_in[1];
    const float* hidden   = (const float*)d_in[2];
    const float* enc      = (const float*)d_in[3];
    const int*   ext_len  = (const int*)  d_in[4];
    const float* emb      = (const float*)d_in[5];
    const float* gru_wih  = (const float*)d_in[6];
    const float* gru_whh  = (const float*)d_in[7];
    const float* gru_bih  = (const float*)d_in[8];
    const float* gru_bhh  = (const float*)d_in[9];
    const float* fc_enc_w = (const float*)d_in[10];
    const float* fc_enc_b = (const float*)d_in[11];
    const float* fc_dec_w = (const float*)d_in[12];
    const float* fc_dec_b = (const float*)d_in[13];
    const float* v_w      = (const float*)d_in[14];
    const float* fc_out1_w= (const float*)d_in[15];
    const float* fc_out1_b= (const float*)d_in[16];
    const float* fc_out2_w= (const float*)d_in[17];
    const float* fc_out2_b= (const float*)d_in[18];
    const float* g1w      = (const float*)d_in[19];
    const float* g1b      = (const float*)d_in[20];
    const float* g2w      = (const float*)d_in[21];
    const float* g2b      = (const float*)d_in[22];
    const float* g3w      = (const float*)d_in[23];
    const float* g3b      = (const float*)d_in[24];
    float* out = (float*)d_out;

    float *p_e1, *p_e2, *p_x, *p_allout, *p_mid, *p_logits;
    cudaGetSymbolAddress((void**)&p_e1,     g_e1);
    cudaGetSymbolAddress((void**)&p_e2,     g_e2);
    cudaGetSymbolAddress((void**)&p_x,      g_x);
    cudaGetSymbolAddress((void**)&p_allout, g_allout);
    cudaGetSymbolAddress((void**)&p_mid,    g_mid);
    cudaGetSymbolAddress((void**)&p_logits, g_logits);
    const float* p_dec = p_x + (size_t)3*ROWS*HH;

    setup_kernel<<<1, 256>>>(tar, hidden);
    embed_kernel<<<ROWS, 128>>>(tar, emb);
    gru_kernel<<<GRU_BLOCKS, 128>>>(gru_wih, gru_whh, gru_bih, gru_bhh);

    // e1 = enc @ fc_enc_w^T + b   [2048, 512]
    sgemm_tn<<<dim3((HH+BN-1)/BN, (BB*SS+BM-1)/BM), 128>>>(enc, fc_enc_w, fc_enc_b, p_e1, BB*SS, HH, HH);
    // e2 = dec_out @ fc_dec_w^T + b  [400, 512]
    sgemm_tn<<<dim3((HH+BN-1)/BN, (ROWS+BM-1)/BM), 128>>>(p_dec, fc_dec_w, fc_dec_b, p_e2, ROWS, HH, HH);

    attn_kernel<<<ROWS, 256>>>(sou, v_w, out);
    weighted_kernel<<<ROWS, 128>>>(enc);
    gate_kernel<<<ROWS, 128>>>(g1w, g1b, g2w, g2b, g3w, g3b);

    // mid = all_out @ fc_out2_w^T + b  [400, 512], K=1024
    sgemm_tn<<<dim3((HH+BN-1)/BN, (ROWS+BM-1)/BM), 128>>>(p_allout, fc_out2_w, fc_out2_b, p_mid, ROWS, HH, 2*HH);
    // logits = mid @ fc_out1_w^T + b  [400, 50256]
    sgemm_tn<<<dim3((NVEXT+BN-1)/BN, (ROWS+BM-1)/BM), 128>>>(p_mid, fc_out1_w, fc_out1_b, p_logits, ROWS, NVEXT, HH);

    stats_kernel<<<ROWS, 256>>>(ext_len);
    gen_kernel<<<dim3((NVEXT+255)/256, ROWS), 256>>>(ext_len, out);
    scatter_kernel<<<ROWS, 256>>>(sou, out);
}

// round 11
// speedup vs baseline: 2.7447x; 1.2637x over previous
#include <cuda_runtime.h>
#include <math.h>

#define BB 8
#define TT 50
#define SS 256
#define HH 512
#define NL 4
#define NVOC 50000
#define NVEXT 50256
#define ROWS (BB*TT)                 /* 400 */
#define OUT_ATT_OFF (ROWS*NVEXT)

// ---------------- device scratch (static: no allocation) ----------------
__device__ float    g_tar_emb[ROWS*HH];
__device__ float    g_x[NL*ROWS*HH];          // per-layer GRU outputs; layer 3 = masked dec_out
__device__ float    g_h2[2][NL*BB*HH];        // double-buffered hidden state
__device__ int      g_len[BB];
__device__ float    g_e1[BB*SS*HH];
__device__ float    g_e2[ROWS*HH];
__device__ float    g_allout[ROWS*2*HH];
__device__ float    g_mid[ROWS*HH];
__device__ float    g_logits[ROWS*NVEXT];
__device__ float    g_atten[ROWS*SS];
__device__ float    g_gate[ROWS];
__device__ float    g_rowmax[ROWS];
__device__ float    g_rowsum[ROWS];
__device__ unsigned g_bar;

// ---------------- setup ----------------
__global__ void setup_kernel(const int* __restrict__ tar, const float* __restrict__ hidden)
{
    int tid = threadIdx.x;
    if (tid == 0) g_bar = 0u;
    if (tid < BB) {
        int c = 0;
        for (int t = 0; t < TT; ++t) c += (tar[tid*TT + t] > 0) ? 1 : 0;
        g_len[tid] = (c < 1) ? 1 : c;
    }
    for (int i = tid; i < NL*BB*HH; i += blockDim.x)
        g_h2[0][i] = hidden[i];
}

// ---------------- embedding gather ----------
__global__ void embed_kernel(const int* __restrict__ tar, const float* __restrict__ emb)
{
    int row = blockIdx.x;
    int tid = threadIdx.x;
    int idx = tar[row];
    float4 v = make_float4(0.f, 0.f, 0.f, 0.f);
    if (idx != 0)
        v = ((const float4*)(emb + (size_t)idx * HH))[tid];
    ((float4*)(g_tar_emb + (size_t)row * HH))[tid] = v;
}

// ---------------- GRU v2: batch-shared weights, k-split warps ----------------
#define GRU_BLOCKS 128
// NOTE: macro params must NOT be named x/y/z/w — member tokens after '.' get substituted.
#define DOT4(acc, u_, v_) acc += (u_).x*(v_).x + (u_).y*(v_).y + (u_).z*(v_).z + (u_).w*(v_).w
#define PHYS(k4) ((k4) ^ (((k4) >> 4) & 7))   /* smem bank swizzle on float4 index */

__global__ void __launch_bounds__(128, 1)
gru_kernel(const float* __restrict__ wih, const float* __restrict__ whh,
           const float* __restrict__ bih, const float* __restrict__ bhh)
{
    const int bid  = blockIdx.x;
    const int l    = bid >> 5;            // 32 blocks per layer
    const int jblk = (bid & 31) << 4;     // 16-wide j slice
    const int tid  = threadIdx.x;
    const int jl   = tid >> 3;            // 0..15
    const int ks   = tid & 7;             // 0..7  (64-k slice)
    const int j    = jblk + jl;

    __shared__ float4 xs4[BB][HH/4];
    __shared__ float4 hs4[BB][HH/4];
    __shared__ int    lens[BB];

    if (tid < BB) lens[tid] = g_len[tid];

    const float4* wiR = (const float4*)(wih + ((size_t)l*3*HH + j) * HH);
    const float4* wiZ = wiR + (HH*HH/4);
    const float4* wiN = wiZ + (HH*HH/4);
    const float4* whR = (const float4*)(whh + ((size_t)l*3*HH + j) * HH);
    const float4* whZ = whR + (HH*HH/4);
    const float4* whN = whZ + (HH*HH/4);

    const float biR = bih[l*3*HH + j];
    const float biZ = bih[l*3*HH + HH + j];
    const float biN = bih[l*3*HH + 2*HH + j];
    const float bhR = bhh[l*3*HH + j];
    const float bhZ = bhh[l*3*HH + HH + j];
    const float bhN = bhh[l*3*HH + 2*HH + j];

    unsigned goal = 0u;
    for (int step = 0; step < TT + NL - 1; ++step) {
        const int t = step - l;
        const int p = step & 1;
        const bool active = (t >= 0) && (t < TT);

        if (active) {
#pragma unroll
            for (int q = 0; q < 8; ++q) {
                int idx = tid + q*128;
                int b  = idx >> 7;
                int k4 = idx & 127;
                const float4* xsrc = (l == 0)
                    ? (const float4*)(g_tar_emb + (size_t)(b*TT + t) * HH)
                    : (const float4*)(g_x + ((size_t)(l-1)*ROWS + b*TT + t) * HH);
                xs4[b][PHYS(k4)] = xsrc[k4];
                hs4[b][PHYS(k4)] = ((const float4*)(g_h2[p] + (size_t)(l*BB + b) * HH))[k4];
            }
            __syncthreads();

            float aR[BB], aZ[BB], aN[BB], cR[BB], cZ[BB], cN[BB];
#pragma unroll
            for (int b = 0; b < BB; ++b) { aR[b]=0.f; aZ[b]=0.f; aN[b]=0.f; cR[b]=0.f; cZ[b]=0.f; cN[b]=0.f; }

#pragma unroll 4
            for (int i = 0; i < 16; ++i) {
                const int k4 = ks*16 + i;
                const float4 wr = wiR[k4], wz = wiZ[k4], wn = wiN[k4];
                const float4 vr = whR[k4], vz = whZ[k4], vn = whN[k4];
                const int kk = PHYS(k4);
#pragma unroll
                for (int b = 0; b < BB; ++b) {
                    const float4 xv = xs4[b][kk];
                    const float4 hv = hs4[b][kk];
                    DOT4(aR[b], wr, xv); DOT4(aZ[b], wz, xv); DOT4(aN[b], wn, xv);
                    DOT4(cR[b], vr, hv); DOT4(cZ[b], vz, hv); DOT4(cN[b], vn, hv);
                }
            }

#pragma unroll
            for (int b = 0; b < BB; ++b) {
#pragma unroll
                for (int o = 1; o < 8; o <<= 1) {
                    aR[b] += __shfl_xor_sync(0xffffffffu, aR[b], o);
                    aZ[b] += __shfl_xor_sync(0xffffffffu, aZ[b], o);
                    aN[b] += __shfl_xor_sync(0xffffffffu, aN[b], o);
                    cR[b] += __shfl_xor_sync(0xffffffffu, cR[b], o);
                    cZ[b] += __shfl_xor_sync(0xffffffffu, cZ[b], o);
                    cN[b] += __shfl_xor_sync(0xffffffffu, cN[b], o);
                }
            }

            if (ks == 0) {
#pragma unroll
                for (int b = 0; b < BB; ++b) {
                    float r = 1.f / (1.f + expf(-(aR[b] + biR + cR[b] + bhR)));
                    float z = 1.f / (1.f + expf(-(aZ[b] + biZ + cZ[b] + bhZ)));
                    float n = tanhf(aN[b] + biN + r * (cN[b] + bhN));
                    float hold = ((const float*)&hs4[b][PHYS(j >> 2)])[j & 3];
                    float hnew = (1.f - z) * n + z * hold;
                    g_h2[p ^ 1][(size_t)(l*BB + b) * HH + j] = hnew;
                    float ov = hnew;
                    if (l == NL-1 && t >= lens[b]) ov = 0.f;
                    g_x[((size_t)l*ROWS + b*TT + t) * HH + j] = ov;
                }
            }
        } else {
            int b  = tid >> 4;
            int j2 = jblk + (tid & 15);
            g_h2[p ^ 1][(size_t)(l*BB + b) * HH + j2] =
                g_h2[p][(size_t)(l*BB + b) * HH + j2];
        }

        __syncthreads();
        if (tid == 0) {
            __threadfence();
            atomicAdd(&g_bar, 1u);
            goal += GRU_BLOCKS;
            while (*(volatile unsigned*)&g_bar < goal) __nanosleep(64);
            __threadfence();
        }
        __syncthreads();
    }
}

// ---------------- SGEMM v2 (fp32, small GEMMs) ----
#define BM 64
#define BN 128
#define BKK 16
__global__ void __launch_bounds__(128, 3)
sgemm_tn(const float* __restrict__ A, const float* __restrict__ W,
         const float* __restrict__ bias, float* __restrict__ C,
         int M, int N, int K)
{
    __shared__ float As[2][BKK][BM + 4];
    __shared__ float Bs[2][BKK][BN + 4];

    const int tid = threadIdx.x;
    const int m0 = blockIdx.y * BM;
    const int n0 = blockIdx.x * BN;
    const int tx = tid & 15;
    const int ty = tid >> 4;

    float acc[8][8];
#pragma unroll
    for (int i = 0; i < 8; ++i)
#pragma unroll
        for (int jj = 0; jj < 8; ++jj) acc[i][jj] = 0.f;

    float4 pa[2], pb[4];

#pragma unroll
    for (int q = 0; q < 2; ++q) {
        int idx = tid + q*128; int row = idx >> 2, kq = idx & 3; int m = m0 + row;
        pa[q] = make_float4(0.f,0.f,0.f,0.f);
        if (m < M) pa[q] = *(const float4*)(A + (size_t)m*K + kq*4);
    }
#pragma unroll
    for (int q = 0; q < 4; ++q) {
        int idx = tid + q*128; int row = idx >> 2, kq = idx & 3; int n = n0 + row;
        pb[q] = make_float4(0.f,0.f,0.f,0.f);
        if (n < N) pb[q] = *(const float4*)(W + (size_t)n*K + kq*4);
    }
#pragma unroll
    for (int q = 0; q < 2; ++q) {
        int idx = tid + q*128; int row = idx >> 2, kq = idx & 3;
        As[0][kq*4+0][row] = pa[q].x; As[0][kq*4+1][row] = pa[q].y;
        As[0][kq*4+2][row] = pa[q].z; As[0][kq*4+3][row] = pa[q].w;
    }
#pragma unroll
    for (int q = 0; q < 4; ++q) {
        int idx = tid + q*128; int row = idx >> 2, kq = idx & 3;
        Bs[0][kq*4+0][row] = pb[q].x; Bs[0][kq*4+1][row] = pb[q].y;
        Bs[0][kq*4+2][row] = pb[q].z; Bs[0][kq*4+3][row] = pb[q].w;
    }
    __syncthreads();

    const int nk = K / BKK;
    for (int kb = 0; kb < nk; ++kb) {
        const int cur = kb & 1, nxt = cur ^ 1;
        const bool more = (kb + 1 < nk);
        if (more) {
            const int k0 = (kb + 1) * BKK;
#pragma unroll
            for (int q = 0; q < 2; ++q) {
                int idx = tid + q*128; int row = idx >> 2, kq = idx & 3; int m = m0 + row;
                pa[q] = make_float4(0.f,0.f,0.f,0.f);
                if (m < M) pa[q] = *(const float4*)(A + (size_t)m*K + k0 + kq*4);
            }
#pragma unroll
            for (int q = 0; q < 4; ++q) {
                int idx = tid + q*128; int row = idx >> 2, kq = idx & 3; int n = n0 + row;
                pb[q] = make_float4(0.f,0.f,0.f,0.f);
                if (n < N) pb[q] = *(const float4*)(W + (size_t)n*K + k0 + kq*4);
            }
        }
#pragma unroll
        for (int k = 0; k < BKK; ++k) {
            float4 a0 = *(const float4*)&As[cur][k][ty*8];
            float4 a1 = *(const float4*)&As[cur][k][ty*8 + 4];
            float4 b0 = *(const float4*)&Bs[cur][k][tx*8];
            float4 b1 = *(const float4*)&Bs[cur][k][tx*8 + 4];
            float av[8] = {a0.x,a0.y,a0.z,a0.w,a1.x,a1.y,a1.z,a1.w};
            float bv[8] = {b0.x,b0.y,b0.z,b0.w,b1.x,b1.y,b1.z,b1.w};
#pragma unroll
            for (int i = 0; i < 8; ++i)
#pragma unroll
                for (int jj = 0; jj < 8; ++jj)
                    acc[i][jj] += av[i] * bv[jj];
        }
        if (more) {
#pragma unroll
            for (int q = 0; q < 2; ++q) {
                int idx = tid + q*128; int row = idx >> 2, kq = idx & 3;
                As[nxt][kq*4+0][row] = pa[q].x; As[nxt][kq*4+1][row] = pa[q].y;
                As[nxt][kq*4+2][row] = pa[q].z; As[nxt][kq*4+3][row] = pa[q].w;
            }
#pragma unroll
            for (int q = 0; q < 4; ++q) {
                int idx = tid + q*128; int row = idx >> 2, kq = idx & 3;
                Bs[nxt][kq*4+0][row] = pb[q].x; Bs[nxt][kq*4+1][row] = pb[q].y;
                Bs[nxt][kq*4+2][row] = pb[q].z; Bs[nxt][kq*4+3][row] = pb[q].w;
            }
        }
        __syncthreads();
    }

#pragma unroll
    for (int i = 0; i < 8; ++i) {
        int m = m0 + ty*8 + i;
        if (m >= M) continue;
#pragma unroll
        for (int jj = 0; jj < 8; ++jj) {
            int n = n0 + tx*8 + jj;
            if (n < N) C[(size_t)m*N + n] = acc[i][jj] + bias[n];
        }
    }
}

// ---------------- tf32 tensor-core GEMM for logits --------------------
// C[m,n] = bias[n] + sum_k A[m,k]*W[n,k]; A row-major (K contig), W row-major
// per n (K contig) == B col-major for mma "row.col". BM=64, BN=128, BK=16.
// 256 threads = 8 warps: warp grid 4(M) x 2(N); warp tile 16 x 64.
// Smem stride 20 floats -> tf32 fragment pattern (g*20+tig) is bank-conflict-free.
#define TM 64
#define TN 128
#define TK 16
#define TSTR 20

__device__ __forceinline__ float f2tf32(float f) {
    unsigned r;
    asm("cvt.rna.tf32.f32 %0, %1;" : "=r"(r) : "f"(f));
    return __uint_as_float(r);
}

__global__ void __launch_bounds__(256, 2)
mma_tf32_tn(const float* __restrict__ A, const float* __restrict__ W,
            const float* __restrict__ bias, float* __restrict__ C,
            int M, int N, int K)
{
    __shared__ float As[2][TM][TSTR];
    __shared__ float Bs[2][TN][TSTR];

    const int tid  = threadIdx.x;
    const int lane = tid & 31;
    const int g    = lane >> 2;      // 0..7
    const int tig  = lane & 3;       // 0..3
    const int warp = tid >> 5;
    const int wM   = warp >> 1;      // 0..3
    const int wN   = warp & 1;       // 0..1

    const int m0 = blockIdx.y * TM;
    const int n0 = blockIdx.x * TN;

    // staging coords (fixed per thread)
    const int arow = tid >> 2;                // 0..63
    const int akq  = (tid & 3) * 4;           // 0,4,8,12
    const bool aok = (m0 + arow) < M;
    const int brow0 = tid >> 2;               // 0..63
    const int brow1 = brow0 + 64;             // 64..127
    const bool bok0 = (n0 + brow0) < N;
    const bool bok1 = (n0 + brow1) < N;

    float c[8][4];
#pragma unroll
    for (int j = 0; j < 8; ++j)
#pragma unroll
        for (int i = 0; i < 4; ++i) c[j][i] = 0.f;

    float4 pa, pb0, pb1;

    // prefetch k-block 0
    pa  = make_float4(0.f,0.f,0.f,0.f);
    pb0 = make_float4(0.f,0.f,0.f,0.f);
    pb1 = make_float4(0.f,0.f,0.f,0.f);
    if (aok)  pa  = *(const float4*)(A + (size_t)(m0 + arow)*K + akq);
    if (bok0) pb0 = *(const float4*)(W + (size_t)(n0 + brow0)*K + akq);
    if (bok1) pb1 = *(const float4*)(W + (size_t)(n0 + brow1)*K + akq);
    {
        float* ad = &As[0][arow][akq];
        ad[0]=f2tf32(pa.x); ad[1]=f2tf32(pa.y); ad[2]=f2tf32(pa.z); ad[3]=f2tf32(pa.w);
        float* b0d = &Bs[0][brow0][akq];
        b0d[0]=f2tf32(pb0.x); b0d[1]=f2tf32(pb0.y); b0d[2]=f2tf32(pb0.z); b0d[3]=f2tf32(pb0.w);
        float* b1d = &Bs[0][brow1][akq];
        b1d[0]=f2tf32(pb1.x); b1d[1]=f2tf32(pb1.y); b1d[2]=f2tf32(pb1.z); b1d[3]=f2tf32(pb1.w);
    }
    __syncthreads();

    const int nk = K / TK;
    for (int kb = 0; kb < nk; ++kb) {
        const int cur = kb & 1, nxt = cur ^ 1;
        const bool more = (kb + 1 < nk);
        if (more) {
            const int k0 = (kb + 1) * TK + akq;
            pa  = make_float4(0.f,0.f,0.f,0.f);
            pb0 = make_float4(0.f,0.f,0.f,0.f);
            pb1 = make_float4(0.f,0.f,0.f,0.f);
            if (aok)  pa  = *(const float4*)(A + (size_t)(m0 + arow)*K + k0);
            if (bok0) pb0 = *(const float4*)(W + (size_t)(n0 + brow0)*K + k0);
            if (bok1) pb1 = *(const float4*)(W + (size_t)(n0 + brow1)*K + k0);
        }

#pragma unroll
        for (int ksub = 0; ksub < 2; ++ksub) {
            const int k8 = ksub * 8;
            const float* Arow0 = &As[cur][wM*16 + g][k8 + tig];
            unsigned a0 = __float_as_uint(Arow0[0]);
            unsigned a1 = __float_as_uint(Arow0[8*TSTR]);
            unsigned a2 = __float_as_uint(Arow0[4]);
            unsigned a3 = __float_as_uint(Arow0[8*TSTR + 4]);
#pragma unroll
            for (int j = 0; j < 8; ++j) {
                const float* Brow = &Bs[cur][wN*64 + j*8 + g][k8 + tig];
                unsigned b0 = __float_as_uint(Brow[0]);
                unsigned b1 = __float_as_uint(Brow[4]);
                asm volatile(
                    "mma.sync.aligned.m16n8k8.row.col.f32.tf32.tf32.f32 "
                    "{%0,%1,%2,%3}, {%4,%5,%6,%7}, {%8,%9}, {%0,%1,%2,%3};\n"
                    : "+f"(c[j][0]), "+f"(c[j][1]), "+f"(c[j][2]), "+f"(c[j][3])
                    : "r"(a0), "r"(a1), "r"(a2), "r"(a3), "r"(b0), "r"(b1));
            }
        }

        if (more) {
            float* ad = &As[nxt][arow][akq];
            ad[0]=f2tf32(pa.x); ad[1]=f2tf32(pa.y); ad[2]=f2tf32(pa.z); ad[3]=f2tf32(pa.w);
            float* b0d = &Bs[nxt][brow0][akq];
            b0d[0]=f2tf32(pb0.x); b0d[1]=f2tf32(pb0.y); b0d[2]=f2tf32(pb0.z); b0d[3]=f2tf32(pb0.w);
            float* b1d = &Bs[nxt][brow1][akq];
            b1d[0]=f2tf32(pb1.x); b1d[1]=f2tf32(pb1.y); b1d[2]=f2tf32(pb1.z); b1d[3]=f2tf32(pb1.w);
        }
        __syncthreads();
    }

    // epilogue: c[j][0..1] -> row (g), cols 2*tig, 2*tig+1; c[j][2..3] -> row g+8
    const int row0 = m0 + wM*16 + g;
    const int row1 = row0 + 8;
#pragma unroll
    for (int j = 0; j < 8; ++j) {
        int n = n0 + wN*64 + j*8 + tig*2;
        if (n < N) {
            float bv = bias[n];
            if (row0 < M) C[(size_t)row0*N + n] = c[j][0] + bv;
            if (row1 < M) C[(size_t)row1*N + n] = c[j][2] + bv;
        }
        if (n + 1 < N) {
            float bv = bias[n+1];
            if (row0 < M) C[(size_t)row0*N + n+1] = c[j][1] + bv;
            if (row1 < M) C[(size_t)row1*N + n+1] = c[j][3] + bv;
        }
    }
}

// ---------------- attention scores + softmax -> atten ----------------
__global__ void __launch_bounds__(256)
attn_kernel(const int* __restrict__ sou, const float* __restrict__ v_w,
            float* __restrict__ out)
{
    const int row = blockIdx.x;
    const int b = row / TT;
    const int tid = threadIdx.x;
    const int warp = tid >> 5, lane = tid & 31;
    const float NEG_INF = __int_as_float(0xff800000);

    __shared__ float e2s[HH];
    __shared__ float vs[HH];
    __shared__ float sc[SS];
    __shared__ float red[8];

    e2s[tid]       = g_e2[(size_t)row*HH + tid];
    e2s[tid + 256] = g_e2[(size_t)row*HH + tid + 256];
    vs[tid]        = v_w[tid];
    vs[tid + 256]  = v_w[tid + 256];
    __syncthreads();

    for (int s = warp; s < SS; s += 8) {
        const float* e1r = g_e1 + ((size_t)(b*SS + s)) * HH;
        float acc = 0.f;
#pragma unroll
        for (int k = 0; k < HH/32; ++k) {
            int h = lane + k*32;
            acc += tanhf(e1r[h] + e2s[h]) * vs[h];
        }
#pragma unroll
        for (int o = 16; o; o >>= 1) acc += __shfl_xor_sync(0xffffffffu, acc, o);
        if (lane == 0)
            sc[s] = (sou[b*SS + s] == 0) ? NEG_INF : acc;
    }
    __syncthreads();

    float v0 = sc[tid];
    float m = v0;
#pragma unroll
    for (int o = 16; o; o >>= 1) m = fmaxf(m, __shfl_xor_sync(0xffffffffu, m, o));
    if (lane == 0) red[warp] = m;
    __syncthreads();
    float M = red[0];
#pragma unroll
    for (int w = 1; w < 8; ++w) M = fmaxf(M, red[w]);
    __syncthreads();
    float e = __expf(v0 - M);
    float ssum = e;
#pragma unroll
    for (int o = 16; o; o >>= 1) ssum += __shfl_xor_sync(0xffffffffu, ssum, o);
    if (lane == 0) red[warp] = ssum;
    __syncthreads();
    float Ssum = 0.f;
#pragma unroll
    for (int w = 0; w < 8; ++w) Ssum += red[w];

    float p = e / Ssum;
    g_atten[(size_t)row*SS + tid] = p;
    out[OUT_ATT_OFF + (size_t)row*SS + tid] = p;
}

// ---------------- weighted = atten @ enc ; build all_out --------------
__global__ void __launch_bounds__(128)
weighted_kernel(const float* __restrict__ enc)
{
    const int row = blockIdx.x;
    const int b = row / TT;
    const int tid = threadIdx.x;

    __shared__ float att[SS];
    att[tid]       = g_atten[(size_t)row*SS + tid];
    att[tid + 128] = g_atten[(size_t)row*SS + tid + 128];
    __syncthreads();

    const float4* encb = (const float4*)enc;
    float4 acc = make_float4(0.f,0.f,0.f,0.f);
#pragma unroll 4
    for (int s = 0; s < SS; ++s) {
        float a = att[s];
        float4 ev = encb[((size_t)(b*SS + s)) * (HH/4) + tid];
        acc.x += a*ev.x; acc.y += a*ev.y; acc.z += a*ev.z; acc.w += a*ev.w;
    }
    float4* ao = (float4*)(g_allout + (size_t)row * 2*HH);
    ao[tid] = acc;
    float4 dv = ((const float4*)(g_x + ((size_t)3*ROWS + row)*HH))[tid];
    ao[HH/4 + tid] = dv;
}

// ---------------- copy gate --------------------------------------------
__global__ void __launch_bounds__(128)
gate_kernel(const float* __restrict__ g1w, const float* __restrict__ g1b,
            const float* __restrict__ g2w, const float* __restrict__ g2b,
            const float* __restrict__ g3w, const float* __restrict__ g3b)
{
    const int row = blockIdx.x;
    const int tid = threadIdx.x;
    const int lane = tid & 31, warp = tid >> 5;
    __shared__ float red[4];

    const float* ao = g_allout + (size_t)row * 2*HH;
    const float* te = g_tar_emb + (size_t)row * HH;
    float part = 0.f;
    for (int i = tid; i < HH; i += 128)
        part += ao[i]*g1w[i] + ao[HH + i]*g2w[i] + te[i]*g3w[i];
#pragma unroll
    for (int o = 16; o; o >>= 1) part += __shfl_xor_sync(0xffffffffu, part, o);
    if (lane == 0) red[warp] = part;
    __syncthreads();
    if (tid == 0) {
        float s = red[0] + red[1] + red[2] + red[3] + g1b[0] + g2b[0] + g3b[0];
        g_gate[row] = 1.f / (1.f + expf(-s));
    }
}

// ---------------- logits row softmax stats ------------------------------
__global__ void __launch_bounds__(256)
stats_kernel(const int* __restrict__ ext_len)
{
    const int row = blockIdx.x;
    const int b = row / TT;
    const int tid = threadIdx.x;
    const int lane = tid & 31, warp = tid >> 5;
    const int limit = NVOC + ext_len[b];
    const float* lr = g_logits + (size_t)row * NVEXT;
    const float NEG_INF = __int_as_float(0xff800000);
    __shared__ float red[8];

    float m = NEG_INF;
    for (int c = tid; c < limit; c += 256) m = fmaxf(m, lr[c]);
#pragma unroll
    for (int o = 16; o; o >>= 1) m = fmaxf(m, __shfl_xor_sync(0xffffffffu, m, o));
    if (lane == 0) red[warp] = m;
    __syncthreads();
    float M = red[0];
#pragma unroll
    for (int w = 1; w < 8; ++w) M = fmaxf(M, red[w]);
    __syncthreads();

    float s = 0.f;
    for (int c = tid; c < limit; c += 256) s += __expf(lr[c] - M);
#pragma unroll
    for (int o = 16; o; o >>= 1) s += __shfl_xor_sync(0xffffffffu, s, o);
    if (lane == 0) red[warp] = s;
    __syncthreads();
    if (tid == 0) {
        float S = 0.f;
#pragma unroll
        for (int w = 0; w < 8; ++w) S += red[w];
        g_rowmax[row] = M;
        g_rowsum[row] = S;
    }
}

// ---------------- (1-gate)*softmax(logits) -> out -----------------------
__global__ void __launch_bounds__(256)
gen_kernel(const int* __restrict__ ext_len, float* __restrict__ out)
{
    const int row = blockIdx.y;
    const int c = blockIdx.x * 256 + threadIdx.x;
    if (c >= NVEXT) return;
    const int b = row / TT;
    const int limit = NVOC + ext_len[b];
    const float gate = g_gate[row];
    float val = 0.f;
    if (c < limit)
        val = __expf(g_logits[(size_t)row*NVEXT + c] - g_rowmax[row]) / g_rowsum[row];
    out[(size_t)row*NVEXT + c] = (1.f - gate) * val;
}

// ---------------- copy mechanism: scatter-add gate*atten ---------------
__global__ void __launch_bounds__(256)
scatter_kernel(const int* __restrict__ sou, float* __restrict__ out)
{
    const int row = blockIdx.x;
    const int b = row / TT;
    const int s = threadIdx.x;
    const float add = g_gate[row] * g_atten[(size_t)row*SS + s];
    atomicAdd(&out[(size_t)row*NVEXT + sou[b*SS + s]], add);
}

// ---------------- launcher ---------------------------------------------
extern "C" void kernel_launch(void* const* d_in, const int* in_sizes, int n_in,
                              void* d_out, int out_size)
{
    const int*   sou      = (const int*)  d_in[0];
    const int*   tar      = (const int*)  d_in[1];
    const float* hidden   = (const float*)d_in[2];
    const float* enc      = (const float*)d_in[3];
    const int*   ext_len  = (const int*)  d_in[4];
    const float* emb      = (const float*)d_in[5];
    const float* gru_wih  = (const float*)d_in[6];
    const float* gru_whh  = (const float*)d_in[7];
    const float* gru_bih  = (const float*)d_in[8];
    const float* gru_bhh  = (const float*)d_in[9];
    const float* fc_enc_w = (const float*)d_in[10];
    const float* fc_enc_b = (const float*)d_in[11];
    const float* fc_dec_w = (const float*)d_in[12];
    const float* fc_dec_b = (const float*)d_in[13];
    const float* v_w      = (const float*)d_in[14];
    const float* fc_out1_w= (const float*)d_in[15];
    const float* fc_out1_b= (const float*)d_in[16];
    const float* fc_out2_w= (const float*)d_in[17];
    const float* fc_out2_b= (const float*)d_in[18];
    const float* g1w      = (const float*)d_in[19];
    const float* g1b      = (const float*)d_in[20];
    const float* g2w      = (const float*)d_in[21];
    const float* g2b      = (const float*)d_in[22];
    const float* g3w      = (const float*)d_in[23];
    const float* g3b      = (const float*)d_in[24];
    float* out = (float*)d_out;

    float *p_e1, *p_e2, *p_x, *p_allout, *p_mid, *p_logits;
    cudaGetSymbolAddress((void**)&p_e1,     g_e1);
    cudaGetSymbolAddress((void**)&p_e2,     g_e2);
    cudaGetSymbolAddress((void**)&p_x,      g_x);
    cudaGetSymbolAddress((void**)&p_allout, g_allout);
    cudaGetSymbolAddress((void**)&p_mid,    g_mid);
    cudaGetSymbolAddress((void**)&p_logits, g_logits);
    const float* p_dec = p_x + (size_t)3*ROWS*HH;

    setup_kernel<<<1, 256>>>(tar, hidden);
    embed_kernel<<<ROWS, 128>>>(tar, emb);
    gru_kernel<<<GRU_BLOCKS, 128>>>(gru_wih, gru_whh, gru_bih, gru_bhh);

    // e1 = enc @ fc_enc_w^T + b   [2048, 512]
    sgemm_tn<<<dim3((HH+BN-1)/BN, (BB*SS+BM-1)/BM), 128>>>(enc, fc_enc_w, fc_enc_b, p_e1, BB*SS, HH, HH);
    // e2 = dec_out @ fc_dec_w^T + b  [400, 512]
    sgemm_tn<<<dim3((HH+BN-1)/BN, (ROWS+BM-1)/BM), 128>>>(p_dec, fc_dec_w, fc_dec_b, p_e2, ROWS, HH, HH);

    attn_kernel<<<ROWS, 256>>>(sou, v_w, out);
    weighted_kernel<<<ROWS, 128>>>(enc);
    gate_kernel<<<ROWS, 128>>>(g1w, g1b, g2w, g2b, g3w, g3b);

    // mid = all_out @ fc_out2_w^T + b  [400, 512], K=1024
    sgemm_tn<<<dim3((HH+BN-1)/BN, (ROWS+BM-1)/BM), 128>>>(p_allout, fc_out2_w, fc_out2_b, p_mid, ROWS, HH, 2*HH);
    // logits = mid @ fc_out1_w^T + b  [400, 50256]  -> tf32 tensor cores
    mma_tf32_tn<<<dim3((NVEXT+TN-1)/TN, (ROWS+TM-1)/TM), 256>>>(p_mid, fc_out1_w, fc_out1_b, p_logits, ROWS, NVEXT, HH);

    stats_kernel<<<ROWS, 256>>>(ext_len);
    gen_kernel<<<dim3((NVEXT+255)/256, ROWS), 256>>>(ext_len, out);
    scatter_kernel<<<ROWS, 256>>>(sou, out);
}